// round 6
// baseline (speedup 1.0000x reference)
#include <cuda_runtime.h>
#include <cuda_bf16.h>
#include <cstdint>

#define GN 2048
#define GB 16
#define GC 128
typedef __nv_bfloat16 bf16;

// ---------------- scratch (static device globals; no allocation) ----------------
__device__ __align__(16) bf16 g_E1h[GB*GC*GN], g_E1l[GB*GC*GN];
__device__ __align__(16) bf16 g_Hh [GB*GC*GN], g_Hl [GB*GC*GN];
__device__ __align__(16) bf16 g_Mh [GB*GC*GN], g_Ml [GB*GC*GN];
__device__ __align__(16) float g_T [GB*GN*GC];
__device__ __align__(16) bf16 g_XCh[GB*3*GC*GN], g_XCl[GB*3*GC*GN];
__device__ __align__(16) bf16 g_XFh[(size_t)GB*1024*GN], g_XFl[(size_t)GB*1024*GN];
__device__ __align__(16) bf16 g_C1h[(size_t)GB*512*GN], g_C1l[(size_t)GB*512*GN];
__device__ __align__(16) bf16 g_C2h[(size_t)GB*256*GN], g_C2l[(size_t)GB*256*GN];
__device__ int   g_IDX [GB*GN*16];
__device__ float g_RMAX[GB*1024], g_RAVG[GB*1024], g_B1[GB*512];
// weight hi/lo planes
__device__ __align__(16) bf16 g_We2h[16384],  g_We2l[16384];
__device__ __align__(16) bf16 g_W1h [49152],  g_W1l [49152];
__device__ __align__(16) bf16 g_W2h [49152],  g_W2l [49152];
__device__ __align__(16) bf16 g_Wfh [393216], g_Wfl [393216];
__device__ __align__(16) bf16 g_Wc1h[1605632],g_Wc1l[1605632];
__device__ __align__(16) bf16 g_Wc2h[131072], g_Wc2l[131072];
__device__ __align__(16) bf16 g_Wc3h[12800],  g_Wc3l[12800];

// ---------------- weight fp32 -> hi/lo bf16 planes ----------------
__global__ void convw_kernel(const float* __restrict__ w, bf16* __restrict__ hi,
                             bf16* __restrict__ lo, int n)
{
    int i = blockIdx.x * 256 + threadIdx.x;
    if (i < n) {
        float x = w[i];
        bf16 h = __float2bfloat16(x);
        hi[i] = h;
        lo[i] = __float2bfloat16(x - __bfloat162float(h));
    }
}

// ---------------- KNN: per-thread register top-16 ----------------
__global__ void knn_kernel(const float* __restrict__ pts, int* __restrict__ idxout)
{
    __shared__ float4 tile[256];
    int b = blockIdx.x;
    int n = blockIdx.y * 128 + threadIdx.x;
    const float* pb = pts + (long long)b * 6 * GN;
    float px = pb[n], py = pb[GN + n], pz = pb[2 * GN + n];
    float sp = px * px + py * py + pz * pz;

    float best[16];
    int   bidx[16];
#pragma unroll
    for (int i = 0; i < 16; ++i) { best[i] = 3.4e38f; bidx[i] = 0; }

    for (int t0 = 0; t0 < GN; t0 += 256) {
        __syncthreads();
        for (int i = threadIdx.x; i < 256; i += 128) {
            int m = t0 + i;
            float qx = pb[m], qy = pb[GN + m], qz = pb[2 * GN + m];
            tile[i] = make_float4(qx, qy, qz, qx * qx + qy * qy + qz * qz);
        }
        __syncthreads();
        for (int i = 0; i < 256; ++i) {
            float4 q = tile[i];
            float d = sp + q.w - 2.0f * (px * q.x + py * q.y + pz * q.z);
            if (d < best[15]) {
                int cand = t0 + i;
                int pos = 0;
#pragma unroll
                for (int k = 0; k < 16; ++k) pos += (best[k] <= d);
#pragma unroll
                for (int k = 15; k > 0; --k) {
                    if (k > pos) { best[k] = best[k - 1]; bidx[k] = bidx[k - 1]; }
                }
#pragma unroll
                for (int k = 0; k < 16; ++k)
                    if (k == pos) { best[k] = d; bidx[k] = cand; }
            }
        }
    }
    int* op = idxout + ((long long)b * GN + n) * 16;
#pragma unroll
    for (int i = 0; i < 16; ++i) op[i] = bidx[i];
}

// ---------------- e1: Cin=6 pointwise conv -> bf16 planes (CN) ----------------
__global__ void e1_kernel(const float* __restrict__ pts, const float* __restrict__ W,
                          const float* __restrict__ g, const float* __restrict__ bb,
                          bf16* __restrict__ oh, bf16* __restrict__ ol)
{
    __shared__ float Wsh[128 * 6];
    __shared__ float gs[128], bs[128];
    int b = blockIdx.x, tid = threadIdx.x;
    int n = blockIdx.y * 256 + tid;
    for (int i = tid; i < 768; i += 256) Wsh[i] = W[i];
    if (tid < 128) { gs[tid] = g[tid]; bs[tid] = bb[tid]; }
    __syncthreads();
    float x[6];
#pragma unroll
    for (int c = 0; c < 6; ++c) x[c] = pts[((long long)b * 6 + c) * GN + n];
    for (int o = 0; o < 128; ++o) {
        float s = 0.f;
#pragma unroll
        for (int c = 0; c < 6; ++c) s += Wsh[o * 6 + c] * x[c];
        s = fmaxf(s * gs[o] + bs[o], 0.f);
        bf16 h = __float2bfloat16(s);
        size_t off = ((size_t)b * 128 + o) * GN + n;
        oh[off] = h;
        ol[off] = __float2bfloat16(s - __bfloat162float(h));
    }
}

// ---------------- tensor-core split-bf16 GEMM ----------------
struct GemmArgs {
    const bf16 *Ah, *Al; int O, Cin, wS;
    const bf16 *Bh, *Bl; long long bS;
    float* oF; long long oS; int oNC;
    bf16 *Yh, *Yl; long long yS;
    const float *pre, *g, *post, *postB;
    const bf16 *rH, *rL; long long rS;
    int act;
};

__device__ __forceinline__ uint32_t s2u(const void* p) {
    return (uint32_t)__cvta_generic_to_shared(p);
}
__device__ __forceinline__ void ldm4(uint32_t* r, uint32_t a) {
    asm volatile("ldmatrix.sync.aligned.m8n8.x4.shared.b16 {%0,%1,%2,%3},[%4];\n"
                 : "=r"(r[0]), "=r"(r[1]), "=r"(r[2]), "=r"(r[3]) : "r"(a));
}
__device__ __forceinline__ void ldm4t(uint32_t* r, uint32_t a) {
    asm volatile("ldmatrix.sync.aligned.m8n8.x4.trans.shared.b16 {%0,%1,%2,%3},[%4];\n"
                 : "=r"(r[0]), "=r"(r[1]), "=r"(r[2]), "=r"(r[3]) : "r"(a));
}
__device__ __forceinline__ void mma16816(float* d, const uint32_t* A, uint32_t b0, uint32_t b1) {
    asm volatile(
        "mma.sync.aligned.m16n8k16.row.col.f32.bf16.bf16.f32 "
        "{%0,%1,%2,%3},{%4,%5,%6,%7},{%8,%9},{%0,%1,%2,%3};\n"
        : "+f"(d[0]), "+f"(d[1]), "+f"(d[2]), "+f"(d[3])
        : "r"(A[0]), "r"(A[1]), "r"(A[2]), "r"(A[3]), "r"(b0), "r"(b1));
}

// smem: A [buf][plane][128][40]bf16 (row 80B)  = 40960B
//       B [buf][plane][32][136]bf16 (row 272B) = 34816B  -> 75776B total
#define SMEM_GEMM 75776
#define SMEM_BOFF 40960

__global__ void __launch_bounds__(256, 2) gemm_mma(GemmArgs A_)
{
    extern __shared__ char sm[];
    const int tid = threadIdx.x, lane = tid & 31, wid = tid >> 5;
    const int wm = wid & 1, wn = wid >> 1;
    const int b = blockIdx.z, n0 = blockIdx.x * 128, o0 = blockIdx.y * 128;
    const bf16* Bhp = A_.Bh + (long long)b * A_.bS + n0;
    const bf16* Blp = A_.Bl + (long long)b * A_.bS + n0;

    float acc[4][4][4];
#pragma unroll
    for (int i = 0; i < 4; ++i)
#pragma unroll
        for (int j = 0; j < 4; ++j)
#pragma unroll
            for (int k = 0; k < 4; ++k) acc[i][j][k] = 0.f;

    const int nch = A_.Cin >> 5;

    // --- async tile loaders ---
    auto issue = [&](int buf, int c0) {
#pragma unroll
        for (int i = 0; i < 4; ++i) {               // A: 1024 16B chunks
            int idx = tid + i * 256;
            int kc = idx & 3, row = (idx >> 2) & 127, p = idx >> 9;
            int o = o0 + row;
            const bf16* base = p ? A_.Al : A_.Ah;
            bool ok = (o < A_.O);
            const bf16* src = ok ? base + (long long)o * A_.wS + c0 + kc * 8 : base;
            uint32_t dst = s2u(sm + (((buf * 2 + p) * 128 + row) * 80 + kc * 16));
            int sz = ok ? 16 : 0;
            asm volatile("cp.async.ca.shared.global [%0],[%1],16,%2;\n"
                         :: "r"(dst), "l"(src), "r"(sz));
        }
#pragma unroll
        for (int i = 0; i < 4; ++i) {               // B: 1024 16B chunks
            int idx = tid + i * 256;
            int kc = idx & 15, row = (idx >> 4) & 31, p = idx >> 9;
            const bf16* src = (p ? Blp : Bhp) + (long long)(c0 + row) * GN + kc * 8;
            uint32_t dst = s2u(sm + SMEM_BOFF + (((buf * 2 + p) * 32 + row) * 272 + kc * 16));
            asm volatile("cp.async.ca.shared.global [%0],[%1],16,16;\n"
                         :: "r"(dst), "l"(src));
        }
        asm volatile("cp.async.commit_group;\n");
    };

    const int g8 = lane >> 3, r8 = lane & 7;
    const int rowIn16 = r8 + (g8 & 1) * 8;    // row within 16-tile for this lane's ldmatrix addr
    const int colOff  = (g8 >> 1) * 8;        // k/n half offset

    auto compute = [&](int buf) {
#pragma unroll
        for (int ks = 0; ks < 2; ++ks) {
            uint32_t ah[4][4], al[4][4];
#pragma unroll
            for (int mt = 0; mt < 4; ++mt) {
                int row = wm * 64 + mt * 16 + rowIn16;
                uint32_t aH = s2u(sm + ((buf * 2 + 0) * 128 + row) * 80 + (ks * 16 + colOff) * 2);
                uint32_t aL = s2u(sm + ((buf * 2 + 1) * 128 + row) * 80 + (ks * 16 + colOff) * 2);
                ldm4(ah[mt], aH);
                ldm4(al[mt], aL);
            }
#pragma unroll
            for (int nt2 = 0; nt2 < 2; ++nt2) {
                int brow = ks * 16 + rowIn16;
                int bcol = wn * 32 + nt2 * 16 + colOff;
                uint32_t bH = s2u(sm + SMEM_BOFF + ((buf * 2 + 0) * 32 + brow) * 272 + bcol * 2);
                uint32_t bL = s2u(sm + SMEM_BOFF + ((buf * 2 + 1) * 32 + brow) * 272 + bcol * 2);
                uint32_t bh[4], bl[4];
                ldm4t(bh, bH);
                ldm4t(bl, bL);
#pragma unroll
                for (int mt = 0; mt < 4; ++mt) {
                    mma16816(acc[mt][nt2 * 2],     ah[mt], bh[0], bh[1]);
                    mma16816(acc[mt][nt2 * 2 + 1], ah[mt], bh[2], bh[3]);
                    mma16816(acc[mt][nt2 * 2],     ah[mt], bl[0], bl[1]);
                    mma16816(acc[mt][nt2 * 2 + 1], ah[mt], bl[2], bl[3]);
                    mma16816(acc[mt][nt2 * 2],     al[mt], bh[0], bh[1]);
                    mma16816(acc[mt][nt2 * 2 + 1], al[mt], bh[2], bh[3]);
                }
            }
        }
    };

    issue(0, 0);
    for (int c = 0; c < nch; ++c) {
        int buf = c & 1;
        if (c + 1 < nch) {
            issue(buf ^ 1, (c + 1) * 32);
            asm volatile("cp.async.wait_group 1;\n");
        } else {
            asm volatile("cp.async.wait_group 0;\n");
        }
        __syncthreads();
        compute(buf);
        __syncthreads();
    }

    // --- epilogue ---
    const int q = lane >> 2, tcol = (lane & 3) * 2;
#pragma unroll
    for (int mt = 0; mt < 4; ++mt) {
        int oBase = o0 + wm * 64 + mt * 16;
#pragma unroll
        for (int hh = 0; hh < 2; ++hh) {
            int o = oBase + q + hh * 8;
            if (o >= A_.O) continue;
            float pr = A_.pre ? A_.pre[o] : 0.f;
            float gg = A_.g ? A_.g[o] : 1.f;
            float po = A_.post ? A_.post[o] : 0.f;
            if (A_.postB) po += A_.postB[b * A_.O + o];
            long long rowOff = (long long)o * GN;
#pragma unroll
            for (int nt = 0; nt < 4; ++nt) {
                int n = n0 + wn * 32 + nt * 8 + tcol;
                float v0 = (acc[mt][nt][hh * 2 + 0] + pr) * gg + po;
                float v1 = (acc[mt][nt][hh * 2 + 1] + pr) * gg + po;
                if (A_.rH) {
                    long long rb = (long long)b * A_.rS + rowOff + n;
                    v0 += __bfloat162float(A_.rH[rb]) + __bfloat162float(A_.rL[rb]);
                    v1 += __bfloat162float(A_.rH[rb + 1]) + __bfloat162float(A_.rL[rb + 1]);
                }
                if (A_.act == 1) { v0 = fmaxf(v0, 0.f); v1 = fmaxf(v1, 0.f); }
                else if (A_.act == 2) { v0 = v0 > 0.f ? v0 : 0.2f * v0; v1 = v1 > 0.f ? v1 : 0.2f * v1; }
                if (A_.Yh) {
                    long long yb = (long long)b * A_.yS + rowOff + n;
                    bf16 h0 = __float2bfloat16(v0), h1 = __float2bfloat16(v1);
                    __nv_bfloat162 hp; hp.x = h0; hp.y = h1;
                    *(__nv_bfloat162*)(A_.Yh + yb) = hp;
                    __nv_bfloat162 lp;
                    lp.x = __float2bfloat16(v0 - __bfloat162float(h0));
                    lp.y = __float2bfloat16(v1 - __bfloat162float(h1));
                    *(__nv_bfloat162*)(A_.Yl + yb) = lp;
                }
                if (A_.oF) {
                    if (A_.oNC) {
                        float* pp = A_.oF + (long long)b * A_.oS;
                        pp[(long long)n * A_.O + o] = v0;
                        pp[(long long)(n + 1) * A_.O + o] = v1;
                    } else {
                        *(float2*)(A_.oF + (long long)b * A_.oS + rowOff + n) = make_float2(v0, v1);
                    }
                }
            }
        }
    }
}

// ---------------- gather + max (T fp32 NC in -> M bf16 planes CN out) ----------------
__global__ void gathermax_kernel(const float* __restrict__ T, const int* __restrict__ IDX,
                                 bf16* __restrict__ Mh, bf16* __restrict__ Ml)
{
    __shared__ float s[8][128];
    int b = blockIdx.x;
    int w = threadIdx.x >> 5, l = threadIdx.x & 31;
    int n0 = blockIdx.y * 8;
    int n = n0 + w;
    const float* tb = T + (size_t)b * GN * 128;
    const int* ib = IDX + ((size_t)b * GN + n) * 16;
    float4 best = make_float4(-3.4e38f, -3.4e38f, -3.4e38f, -3.4e38f);
#pragma unroll
    for (int k = 0; k < 16; ++k) {
        int j = ib[k];
        float4 v = *((const float4*)(tb + (size_t)j * 128) + l);
        best.x = fmaxf(best.x, v.x); best.y = fmaxf(best.y, v.y);
        best.z = fmaxf(best.z, v.z); best.w = fmaxf(best.w, v.w);
    }
    ((float4*)s[w])[l] = best;
    __syncthreads();
    int c = threadIdx.x;
    if (c < 128) {
        __align__(16) bf16 hi8[8];
        __align__(16) bf16 lo8[8];
#pragma unroll
        for (int j = 0; j < 8; ++j) {
            float v = s[j][c];
            bf16 h = __float2bfloat16(v);
            hi8[j] = h;
            lo8[j] = __float2bfloat16(v - __bfloat162float(h));
        }
        size_t off = ((size_t)b * 128 + c) * GN + n0;
        *(uint4*)(Mh + off) = *(uint4*)hi8;
        *(uint4*)(Ml + off) = *(uint4*)lo8;
    }
}

// ---------------- row max+mean over N for XF (reconstruct hi+lo) ----------------
__global__ void reduce_kernel(const bf16* __restrict__ XFh, const bf16* __restrict__ XFl,
                              float* __restrict__ RMAX, float* __restrict__ RAVG)
{
    int r = blockIdx.x * 8 + (threadIdx.x >> 5);
    int l = threadIdx.x & 31;
    const uint4* ph = (const uint4*)(XFh + (size_t)r * GN);
    const uint4* pl = (const uint4*)(XFl + (size_t)r * GN);
    float mx = -3.4e38f, sm = 0.f;
#pragma unroll
    for (int t = 0; t < 8; ++t) {
        uint4 H = ph[l + 32 * t], L = pl[l + 32 * t];
        const uint32_t* hw = (const uint32_t*)&H;
        const uint32_t* lw = (const uint32_t*)&L;
#pragma unroll
        for (int i = 0; i < 4; ++i) {
            float2 fh = __bfloat1622float2(*(const __nv_bfloat162*)&hw[i]);
            float2 fl = __bfloat1622float2(*(const __nv_bfloat162*)&lw[i]);
            float v0 = fh.x + fl.x, v1 = fh.y + fl.y;
            mx = fmaxf(mx, fmaxf(v0, v1));
            sm += v0 + v1;
        }
    }
#pragma unroll
    for (int off = 16; off; off >>= 1) {
        mx = fmaxf(mx, __shfl_xor_sync(0xffffffffu, mx, off));
        sm += __shfl_xor_sync(0xffffffffu, sm, off);
    }
    if (!l) { RMAX[r] = mx; RAVG[r] = sm * (1.f / GN); }
}

// ---------------- per-batch bias for c1 ----------------
__global__ void bias1_kernel(const float* __restrict__ Wc1, const float* __restrict__ bc1,
                             const float* __restrict__ gc1, const float* __restrict__ bb1,
                             const float* __restrict__ Wl, const float* __restrict__ gl,
                             const float* __restrict__ bl, const float* __restrict__ label,
                             const float* __restrict__ RMAX, const float* __restrict__ RAVG,
                             float* __restrict__ B1)
{
    int b = blockIdx.x;
    int tid = threadIdx.x, warp = tid >> 5, lane = tid & 31;
    __shared__ float lab[64];
    if (tid < 64) {
        float s = 0.f;
#pragma unroll
        for (int i = 0; i < 16; ++i) s += Wl[tid * 16 + i] * label[b * 16 + i];
        s = s * gl[tid] + bl[tid];
        lab[tid] = s > 0.f ? s : 0.2f * s;
    }
    __syncthreads();
    int o = blockIdx.y * 8 + warp;
    const float* wr = Wc1 + (long long)o * 3136;
    const float* xm = RMAX + b * 1024;
    const float* xa = RAVG + b * 1024;
    float s = 0.f;
    for (int j = lane; j < 1024; j += 32)
        s += wr[1024 + j] * xm[j] + wr[2048 + j] * xa[j];
    for (int j = lane; j < 64; j += 32)
        s += wr[3072 + j] * lab[j];
#pragma unroll
    for (int off = 16; off; off >>= 1) s += __shfl_xor_sync(0xffffffffu, s, off);
    if (!lane) B1[b * 512 + o] = gc1[o] * (s + bc1[o]) + bb1[o];
}

// ---------------- host side ----------------
template <class T>
static T* symp(const void* s) { void* p = nullptr; cudaGetSymbolAddress(&p, s); return (T*)p; }

static void run_gemm(const bf16* Ah, const bf16* Al, int O, int Cin, int wS,
                     const bf16* Bh, const bf16* Bl, long long bS,
                     float* oF, long long oS, int oNC,
                     bf16* Yh, bf16* Yl, long long yS,
                     const float* pre, const float* g, const float* post, const float* postB,
                     const bf16* rH, const bf16* rL, long long rS, int act)
{
    GemmArgs a;
    a.Ah = Ah; a.Al = Al; a.O = O; a.Cin = Cin; a.wS = wS;
    a.Bh = Bh; a.Bl = Bl; a.bS = bS;
    a.oF = oF; a.oS = oS; a.oNC = oNC;
    a.Yh = Yh; a.Yl = Yl; a.yS = yS;
    a.pre = pre; a.g = g; a.post = post; a.postB = postB;
    a.rH = rH; a.rL = rL; a.rS = rS; a.act = act;
    dim3 grid(GN / 128, (O + 127) / 128, GB);
    gemm_mma<<<grid, 256, SMEM_GEMM>>>(a);
}

static void conv_w(const float* w, bf16* hi, bf16* lo, int n)
{
    convw_kernel<<<(n + 255) / 256, 256>>>(w, hi, lo, n);
}

extern "C" void kernel_launch(void* const* d_in, const int* in_sizes, int n_in,
                              void* d_out, int out_size)
{
    const float* pts   = (const float*)d_in[0];
    const float* label = (const float*)d_in[1];
    const float* We1   = (const float*)d_in[2];
    const float* ge1   = (const float*)d_in[3];
    const float* be1   = (const float*)d_in[4];
    const float* We2   = (const float*)d_in[5];
    const float* ge2   = (const float*)d_in[6];
    const float* be2   = (const float*)d_in[7];
    const float* W1    = (const float*)d_in[8];
    const float* g1    = (const float*)d_in[9];
    const float* b1    = (const float*)d_in[10];
    const float* W2    = (const float*)d_in[11];
    const float* g2    = (const float*)d_in[12];
    const float* b2    = (const float*)d_in[13];
    const float* Wf    = (const float*)d_in[14];
    const float* gf    = (const float*)d_in[15];
    const float* bf_   = (const float*)d_in[16];
    const float* Wl    = (const float*)d_in[17];
    const float* gl    = (const float*)d_in[18];
    const float* bl    = (const float*)d_in[19];
    const float* Wc1   = (const float*)d_in[20];
    const float* bc1   = (const float*)d_in[21];
    const float* gc1   = (const float*)d_in[22];
    const float* bb1   = (const float*)d_in[23];
    const float* Wc2   = (const float*)d_in[24];
    const float* bc2   = (const float*)d_in[25];
    const float* gc2   = (const float*)d_in[26];
    const float* bb2   = (const float*)d_in[27];
    const float* Wc3   = (const float*)d_in[28];
    const float* bc3   = (const float*)d_in[29];
    float* out = (float*)d_out;

    cudaFuncSetAttribute(gemm_mma, cudaFuncAttributeMaxDynamicSharedMemorySize, SMEM_GEMM);

    bf16 *E1h = symp<bf16>(g_E1h), *E1l = symp<bf16>(g_E1l);
    bf16 *Hh  = symp<bf16>(g_Hh),  *Hl  = symp<bf16>(g_Hl);
    bf16 *Mh  = symp<bf16>(g_Mh),  *Ml  = symp<bf16>(g_Ml);
    bf16 *XCh = symp<bf16>(g_XCh), *XCl = symp<bf16>(g_XCl);
    bf16 *XFh = symp<bf16>(g_XFh), *XFl = symp<bf16>(g_XFl);
    bf16 *C1h = symp<bf16>(g_C1h), *C1l = symp<bf16>(g_C1l);
    bf16 *C2h = symp<bf16>(g_C2h), *C2l = symp<bf16>(g_C2l);
    float* T    = symp<float>(g_T);
    float* RMAX = symp<float>(g_RMAX);
    float* RAVG = symp<float>(g_RAVG);
    float* B1   = symp<float>(g_B1);
    int*   IDX  = symp<int>(g_IDX);
    bf16 *We2h = symp<bf16>(g_We2h), *We2l = symp<bf16>(g_We2l);
    bf16 *W1h  = symp<bf16>(g_W1h),  *W1l  = symp<bf16>(g_W1l);
    bf16 *W2h  = symp<bf16>(g_W2h),  *W2l  = symp<bf16>(g_W2l);
    bf16 *Wfh  = symp<bf16>(g_Wfh),  *Wfl  = symp<bf16>(g_Wfl);
    bf16 *Wc1h = symp<bf16>(g_Wc1h), *Wc1l = symp<bf16>(g_Wc1l);
    bf16 *Wc2h = symp<bf16>(g_Wc2h), *Wc2l = symp<bf16>(g_Wc2l);
    bf16 *Wc3h = symp<bf16>(g_Wc3h), *Wc3l = symp<bf16>(g_Wc3l);

    // weight conversion
    conv_w(We2, We2h, We2l, 16384);
    conv_w(W1,  W1h,  W1l,  49152);
    conv_w(W2,  W2h,  W2l,  49152);
    conv_w(Wf,  Wfh,  Wfl,  393216);
    conv_w(Wc1, Wc1h, Wc1l, 1605632);
    conv_w(Wc2, Wc2h, Wc2l, 131072);
    conv_w(Wc3, Wc3h, Wc3l, 12800);

    // 1. KNN
    knn_kernel<<<dim3(GB, GN / 128), 128>>>(pts, IDX);

    // 2. embedding
    e1_kernel<<<dim3(GB, GN / 256), 256>>>(pts, We1, ge1, be1, E1h, E1l);
    run_gemm(We2h, We2l, 128, 128, 128, E1h, E1l, 128LL * GN,
             nullptr, 0, 0, Hh, Hl, 128LL * GN,
             nullptr, ge2, be2, nullptr, nullptr, nullptr, 0, 1);

    // 3. three edge blocks
    const bf16 *hH = Hh, *hL = Hl;
    long long hB = 128LL * GN;
    for (int i = 0; i < 3; ++i) {
        // t = relu(bn(W1 h))   -> fp32 NC layout for gather
        run_gemm(W1h + (long long)i * 16384, W1l + (long long)i * 16384, 128, 128, 128,
                 hH, hL, hB,
                 T, 128LL * GN, 1, nullptr, nullptr, 0,
                 nullptr, g1 + i * 128, b1 + i * 128, nullptr, nullptr, nullptr, 0, 1);
        gathermax_kernel<<<dim3(GB, GN / 8), 256>>>(T, IDX, Mh, Ml);
        // h = relu(bn(W2 m) + h)  -> XCAT segment planes
        run_gemm(W2h + (long long)i * 16384, W2l + (long long)i * 16384, 128, 128, 128,
                 Mh, Ml, 128LL * GN,
                 nullptr, 0, 0,
                 XCh + (long long)i * 128 * GN, XCl + (long long)i * 128 * GN, 384LL * GN,
                 nullptr, g2 + i * 128, b2 + i * 128, nullptr, hH, hL, hB, 1);
        hH = XCh + (long long)i * 128 * GN;
        hL = XCl + (long long)i * 128 * GN;
        hB = 384LL * GN;
    }

    // 4. xf = leaky(bn(Wf @ xcat))
    run_gemm(Wfh, Wfl, 1024, 384, 384, XCh, XCl, 384LL * GN,
             nullptr, 0, 0, XFh, XFl, 1024LL * GN,
             nullptr, gf, bf_, nullptr, nullptr, nullptr, 0, 2);

    // 5. global reductions + per-batch bias for c1
    reduce_kernel<<<GB * 1024 / 8, 256>>>(XFh, XFl, RMAX, RAVG);
    bias1_kernel<<<dim3(GB, 64), 256>>>(Wc1, bc1, gc1, bb1, Wl, gl, bl, label,
                                        RMAX, RAVG, B1);

    // 6. c1 = relu(gc1 * Wc1[:, :1024]@xf + per-batch bias)
    run_gemm(Wc1h, Wc1l, 512, 1024, 3136, XFh, XFl, 1024LL * GN,
             nullptr, 0, 0, C1h, C1l, 512LL * GN,
             nullptr, gc1, nullptr, B1, nullptr, nullptr, 0, 1);

    // 7. c2 = relu((Wc2@c1 + bc2)*gc2 + bb2)
    run_gemm(Wc2h, Wc2l, 256, 512, 512, C1h, C1l, 512LL * GN,
             nullptr, 0, 0, C2h, C2l, 256LL * GN,
             bc2, gc2, bb2, nullptr, nullptr, nullptr, 0, 1);

    // 8. out = Wc3@c2 + bc3
    run_gemm(Wc3h, Wc3l, 50, 256, 256, C2h, C2l, 256LL * GN,
             out, 50LL * GN, 0, nullptr, nullptr, 0,
             bc3, nullptr, nullptr, nullptr, nullptr, nullptr, 0, 0);
}

// round 9
// speedup vs baseline: 1.4793x; 1.4793x over previous
#include <cuda_runtime.h>
#include <cuda_fp16.h>
#include <cstdint>

#define GN 2048
#define GB 16
typedef __half half_t;

// ---------------- scratch (static device globals; no allocation) ----------------
// Activations channel-major (CN): X[(b*C + c)*GN + n], single fp16 plane.
__device__ __align__(16) half_t g_E1[GB*128*GN];
__device__ __align__(16) half_t g_H [GB*128*GN];
__device__ __align__(16) half_t g_M [GB*128*GN];
__device__ __align__(16) half_t g_T [(size_t)GB*GN*128];           // NC for gather
__device__ __align__(16) half_t g_XC[(size_t)GB*384*GN];
__device__ __align__(16) half_t g_XF[(size_t)GB*1024*GN];
__device__ __align__(16) half_t g_C1[(size_t)GB*512*GN];
__device__ __align__(16) half_t g_C2[(size_t)GB*256*GN];
__device__ int   g_IDX [GB*GN*16];
__device__ float g_RMAX[GB*1024], g_RAVG[GB*1024], g_B1[GB*512];
// fp16 weights
__device__ __align__(16) half_t g_We2[16384];
__device__ __align__(16) half_t g_W1 [49152];
__device__ __align__(16) half_t g_W2 [49152];
__device__ __align__(16) half_t g_Wf [393216];
__device__ __align__(16) half_t g_Wc1[1605632];
__device__ __align__(16) half_t g_Wc2[131072];
__device__ __align__(16) half_t g_Wc3[12800];

// ---------------- weight fp32 -> fp16 ----------------
__global__ void convw_kernel(const float* __restrict__ w, half_t* __restrict__ o, int n)
{
    int i = blockIdx.x * 256 + threadIdx.x;
    if (i < n) o[i] = __float2half_rn(w[i]);
}

// ---------------- KNN: per-thread register top-16 ----------------
__global__ void knn_kernel(const float* __restrict__ pts, int* __restrict__ idxout)
{
    __shared__ float4 tile[256];
    int b = blockIdx.x;
    int n = blockIdx.y * 128 + threadIdx.x;
    const float* pb = pts + (long long)b * 6 * GN;
    float px = pb[n], py = pb[GN + n], pz = pb[2 * GN + n];
    float sp = px * px + py * py + pz * pz;

    float best[16];
    int   bidx[16];
#pragma unroll
    for (int i = 0; i < 16; ++i) { best[i] = 3.4e38f; bidx[i] = 0; }

    for (int t0 = 0; t0 < GN; t0 += 256) {
        __syncthreads();
        for (int i = threadIdx.x; i < 256; i += 128) {
            int m = t0 + i;
            float qx = pb[m], qy = pb[GN + m], qz = pb[2 * GN + m];
            tile[i] = make_float4(qx, qy, qz, qx * qx + qy * qy + qz * qz);
        }
        __syncthreads();
        for (int i = 0; i < 256; ++i) {
            float4 q = tile[i];
            float d = sp + q.w - 2.0f * (px * q.x + py * q.y + pz * q.z);
            if (d < best[15]) {
                int cand = t0 + i;
                int pos = 0;
#pragma unroll
                for (int k = 0; k < 16; ++k) pos += (best[k] <= d);
#pragma unroll
                for (int k = 15; k > 0; --k) {
                    if (k > pos) { best[k] = best[k - 1]; bidx[k] = bidx[k - 1]; }
                }
#pragma unroll
                for (int k = 0; k < 16; ++k)
                    if (k == pos) { best[k] = d; bidx[k] = cand; }
            }
        }
    }
    int* op = idxout + ((long long)b * GN + n) * 16;
#pragma unroll
    for (int i = 0; i < 16; ++i) op[i] = bidx[i];
}

// ---------------- e1: Cin=6 pointwise conv -> fp16 (CN) ----------------
__global__ void e1_kernel(const float* __restrict__ pts, const float* __restrict__ W,
                          const float* __restrict__ g, const float* __restrict__ bb,
                          half_t* __restrict__ out)
{
    __shared__ float Wsh[768], gs[128], bs[128];
    int b = blockIdx.x, tid = threadIdx.x;
    int n = blockIdx.y * 256 + tid;
    for (int i = tid; i < 768; i += 256) Wsh[i] = W[i];
    if (tid < 128) { gs[tid] = g[tid]; bs[tid] = bb[tid]; }
    __syncthreads();
    float x[6];
#pragma unroll
    for (int c = 0; c < 6; ++c) x[c] = pts[((long long)b * 6 + c) * GN + n];
    for (int o = 0; o < 128; ++o) {
        float s = 0.f;
#pragma unroll
        for (int c = 0; c < 6; ++c) s += Wsh[o * 6 + c] * x[c];
        s = fmaxf(s * gs[o] + bs[o], 0.f);
        out[((size_t)b * 128 + o) * GN + n] = __float2half_rn(s);
    }
}

// ---------------- fp16 tensor-core GEMM (mma.sync) ----------------
struct GemmArgs {
    const half_t* A; int O, Cin, wS;        // weights, row-major O x wS
    const half_t* B; long long bS;          // activations CN
    float* oF; long long oS;                // optional fp32 CN out
    half_t* oT;                             // optional fp16 NC out (T for gather)
    half_t* Y; long long yS;                // fp16 CN out
    const float *pre, *g, *post, *postB;
    const half_t* R; long long rS;          // residual CN fp16
    int act;
};

__device__ __forceinline__ uint32_t s2u(const void* p) {
    return (uint32_t)__cvta_generic_to_shared(p);
}
__device__ __forceinline__ void ldm4(uint32_t* r, uint32_t a) {
    asm volatile("ldmatrix.sync.aligned.m8n8.x4.shared.b16 {%0,%1,%2,%3},[%4];\n"
                 : "=r"(r[0]), "=r"(r[1]), "=r"(r[2]), "=r"(r[3]) : "r"(a));
}
__device__ __forceinline__ void ldm4t(uint32_t* r, uint32_t a) {
    asm volatile("ldmatrix.sync.aligned.m8n8.x4.trans.shared.b16 {%0,%1,%2,%3},[%4];\n"
                 : "=r"(r[0]), "=r"(r[1]), "=r"(r[2]), "=r"(r[3]) : "r"(a));
}
__device__ __forceinline__ void mma16816(float* d, const uint32_t* A, uint32_t b0, uint32_t b1) {
    asm volatile(
        "mma.sync.aligned.m16n8k16.row.col.f32.f16.f16.f32 "
        "{%0,%1,%2,%3},{%4,%5,%6,%7},{%8,%9},{%0,%1,%2,%3};\n"
        : "+f"(d[0]), "+f"(d[1]), "+f"(d[2]), "+f"(d[3])
        : "r"(A[0]), "r"(A[1]), "r"(A[2]), "r"(A[3]), "r"(b0), "r"(b1));
}

// smem: A [buf][128][40]half (row 80B) = 20480B ; B [buf][32][136]half (row 272B) = 17408B
#define SMEM_GEMM 37888
#define SMEM_BOFF 20480

__global__ void __launch_bounds__(256, 2) gemm_mma(GemmArgs A_)
{
    extern __shared__ char sm[];
    const int tid = threadIdx.x, lane = tid & 31, wid = tid >> 5;
    const int wm = wid & 1, wn = wid >> 1;
    const int b = blockIdx.z, n0 = blockIdx.x * 128, o0 = blockIdx.y * 128;
    const half_t* Bp = A_.B + (long long)b * A_.bS + n0;

    float acc[4][4][4];
#pragma unroll
    for (int i = 0; i < 4; ++i)
#pragma unroll
        for (int j = 0; j < 4; ++j)
#pragma unroll
            for (int k = 0; k < 4; ++k) acc[i][j][k] = 0.f;

    const int nch = A_.Cin >> 5;

    auto issue = [&](int buf, int c0) {
#pragma unroll
        for (int e = 0; e < 2; ++e) {               // A: 512 16B chunks
            int idx = tid + e * 256;
            int kc = idx & 3, row = idx >> 2;
            int o = o0 + row;
            bool ok = (o < A_.O);
            const half_t* src = ok ? A_.A + (long long)o * A_.wS + c0 + kc * 8 : A_.A;
            uint32_t dst = s2u(sm + ((buf * 128 + row) * 80 + kc * 16));
            int sz = ok ? 16 : 0;
            asm volatile("cp.async.ca.shared.global [%0],[%1],16,%2;\n"
                         :: "r"(dst), "l"(src), "r"(sz));
        }
#pragma unroll
        for (int e = 0; e < 2; ++e) {               // B: 512 16B chunks
            int idx = tid + e * 256;
            int kc = idx & 15, row = idx >> 4;
            const half_t* src = Bp + (long long)(c0 + row) * GN + kc * 8;
            uint32_t dst = s2u(sm + SMEM_BOFF + ((buf * 32 + row) * 272 + kc * 16));
            asm volatile("cp.async.ca.shared.global [%0],[%1],16,16;\n"
                         :: "r"(dst), "l"(src));
        }
        asm volatile("cp.async.commit_group;\n");
    };

    const int g8 = lane >> 3, r8 = lane & 7;
    const int rowIn16 = r8 + (g8 & 1) * 8;
    const int colOff  = (g8 >> 1) * 8;

    auto compute = [&](int buf) {
#pragma unroll
        for (int ks = 0; ks < 2; ++ks) {
            uint32_t ah[4][4];
#pragma unroll
            for (int mt = 0; mt < 4; ++mt) {
                int row = wm * 64 + mt * 16 + rowIn16;
                uint32_t aH = s2u(sm + (buf * 128 + row) * 80 + (ks * 16 + colOff) * 2);
                ldm4(ah[mt], aH);
            }
#pragma unroll
            for (int nt2 = 0; nt2 < 2; ++nt2) {
                int brow = ks * 16 + rowIn16;
                int bcol = wn * 32 + nt2 * 16 + colOff;
                uint32_t bH = s2u(sm + SMEM_BOFF + (buf * 32 + brow) * 272 + bcol * 2);
                uint32_t bh[4];
                ldm4t(bh, bH);
#pragma unroll
                for (int mt = 0; mt < 4; ++mt) {
                    mma16816(acc[mt][nt2 * 2],     ah[mt], bh[0], bh[1]);
                    mma16816(acc[mt][nt2 * 2 + 1], ah[mt], bh[2], bh[3]);
                }
            }
        }
    };

    issue(0, 0);
    for (int c = 0; c < nch; ++c) {
        int buf = c & 1;
        if (c + 1 < nch) {
            issue(buf ^ 1, (c + 1) * 32);
            asm volatile("cp.async.wait_group 1;\n");
        } else {
            asm volatile("cp.async.wait_group 0;\n");
        }
        __syncthreads();
        compute(buf);
        __syncthreads();
    }

    // --- epilogue ---
    const int q = lane >> 2, tcol = (lane & 3) * 2;
#pragma unroll
    for (int mt = 0; mt < 4; ++mt) {
        int oBase = o0 + wm * 64 + mt * 16;
#pragma unroll
        for (int hh = 0; hh < 2; ++hh) {
            int o = oBase + q + hh * 8;
            if (o >= A_.O) continue;
            float pr = A_.pre  ? A_.pre[o]           : 0.f;
            float gg = A_.g    ? A_.g[o]             : 1.f;
            float po = A_.post ? A_.post[o]          : 0.f;
            if (A_.postB) po += A_.postB[b * A_.O + o];
            long long rowOff = (long long)o * GN;
#pragma unroll
            for (int nt = 0; nt < 4; ++nt) {
                int n = n0 + wn * 32 + nt * 8 + tcol;
                float v0 = (acc[mt][nt][hh * 2 + 0] + pr) * gg + po;
                float v1 = (acc[mt][nt][hh * 2 + 1] + pr) * gg + po;
                if (A_.R) {
                    const __half2 r2 = *(const __half2*)(A_.R + (long long)b * A_.rS + rowOff + n);
                    float2 rf = __half22float2(r2);
                    v0 += rf.x; v1 += rf.y;
                }
                if (A_.act == 1) { v0 = fmaxf(v0, 0.f); v1 = fmaxf(v1, 0.f); }
                else if (A_.act == 2) { v0 = v0 > 0.f ? v0 : 0.2f * v0; v1 = v1 > 0.f ? v1 : 0.2f * v1; }
                if (A_.Y) {
                    __half2 hp = __floats2half2_rn(v0, v1);
                    *(__half2*)(A_.Y + (long long)b * A_.yS + rowOff + n) = hp;
                }
                if (A_.oT) {   // fp16 NC (point-major) for gather
                    half_t* pp = A_.oT + ((long long)b * GN) * 128;
                    pp[(long long)n * 128 + o] = __float2half_rn(v0);
                    pp[(long long)(n + 1) * 128 + o] = __float2half_rn(v1);
                }
                if (A_.oF) {
                    *(float2*)(A_.oF + (long long)b * A_.oS + rowOff + n) = make_float2(v0, v1);
                }
            }
        }
    }
}

// ---------------- gather + max (T fp16 NC in -> M fp16 CN out) ----------------
__global__ void gathermax_kernel(const half_t* __restrict__ T, const int* __restrict__ IDX,
                                 half_t* __restrict__ M)
{
    __shared__ float s[8][128];
    int b = blockIdx.x;
    int w = threadIdx.x >> 5, l = threadIdx.x & 31;
    int n0 = blockIdx.y * 8;
    int n = n0 + w;
    const half_t* tb = T + (size_t)b * GN * 128;
    const int* ib = IDX + ((size_t)b * GN + n) * 16;
    float4 best = make_float4(-3.4e38f, -3.4e38f, -3.4e38f, -3.4e38f);
#pragma unroll
    for (int k = 0; k < 16; ++k) {
        int j = ib[k];
        uint2 u = *((const uint2*)(tb + (size_t)j * 128) + l);   // 4 halves
        float2 a = __half22float2(*(__half2*)&u.x);
        float2 c = __half22float2(*(__half2*)&u.y);
        best.x = fmaxf(best.x, a.x); best.y = fmaxf(best.y, a.y);
        best.z = fmaxf(best.z, c.x); best.w = fmaxf(best.w, c.y);
    }
    s[w][l * 4 + 0] = best.x; s[w][l * 4 + 1] = best.y;
    s[w][l * 4 + 2] = best.z; s[w][l * 4 + 3] = best.w;
    __syncthreads();
    int c = threadIdx.x;
    if (c < 128) {
        __align__(16) half_t h8[8];
#pragma unroll
        for (int j = 0; j < 8; ++j) h8[j] = __float2half_rn(s[j][c]);
        *(uint4*)(M + ((size_t)b * 128 + c) * GN + n0) = *(uint4*)h8;
    }
}

// ---------------- row max+mean over N for XF (CN fp16) ----------------
__global__ void reduce_kernel(const half_t* __restrict__ XF,
                              float* __restrict__ RMAX, float* __restrict__ RAVG)
{
    int r = blockIdx.x * 8 + (threadIdx.x >> 5);
    int l = threadIdx.x & 31;
    const uint4* p = (const uint4*)(XF + (size_t)r * GN);   // 8 halves per uint4
    float mx = -3.4e38f, sm = 0.f;
#pragma unroll
    for (int t = 0; t < 8; ++t) {
        uint4 u = p[l + 32 * t];
        const uint32_t* uw = (const uint32_t*)&u;
#pragma unroll
        for (int i = 0; i < 4; ++i) {
            float2 f = __half22float2(*(const __half2*)&uw[i]);
            mx = fmaxf(mx, fmaxf(f.x, f.y));
            sm += f.x + f.y;
        }
    }
#pragma unroll
    for (int off = 16; off; off >>= 1) {
        mx = fmaxf(mx, __shfl_xor_sync(0xffffffffu, mx, off));
        sm += __shfl_xor_sync(0xffffffffu, sm, off);
    }
    if (!l) { RMAX[r] = mx; RAVG[r] = sm * (1.f / GN); }
}

// ---------------- per-batch bias for c1 ----------------
__global__ void bias1_kernel(const float* __restrict__ Wc1, const float* __restrict__ bc1,
                             const float* __restrict__ gc1, const float* __restrict__ bb1,
                             const float* __restrict__ Wl, const float* __restrict__ gl,
                             const float* __restrict__ bl, const float* __restrict__ label,
                             const float* __restrict__ RMAX, const float* __restrict__ RAVG,
                             float* __restrict__ B1)
{
    int b = blockIdx.x;
    int tid = threadIdx.x, warp = tid >> 5, lane = tid & 31;
    __shared__ float lab[64];
    if (tid < 64) {
        float s = 0.f;
#pragma unroll
        for (int i = 0; i < 16; ++i) s += Wl[tid * 16 + i] * label[b * 16 + i];
        s = s * gl[tid] + bl[tid];
        lab[tid] = s > 0.f ? s : 0.2f * s;
    }
    __syncthreads();
    int o = blockIdx.y * 8 + warp;
    const float* wr = Wc1 + (long long)o * 3136;
    const float* xm = RMAX + b * 1024;
    const float* xa = RAVG + b * 1024;
    float s = 0.f;
    for (int j = lane; j < 1024; j += 32)
        s += wr[1024 + j] * xm[j] + wr[2048 + j] * xa[j];
    for (int j = lane; j < 64; j += 32)
        s += wr[3072 + j] * lab[j];
#pragma unroll
    for (int off = 16; off; off >>= 1) s += __shfl_xor_sync(0xffffffffu, s, off);
    if (!lane) B1[b * 512 + o] = gc1[o] * (s + bc1[o]) + bb1[o];
}

// ---------------- host side ----------------
template <class T>
static T* symp(const void* s) { void* p = nullptr; cudaGetSymbolAddress(&p, s); return (T*)p; }

static void run_gemm(const half_t* A, int O, int Cin, int wS,
                     const half_t* B, long long bS,
                     float* oF, long long oS, half_t* oT,
                     half_t* Y, long long yS,
                     const float* pre, const float* g, const float* post, const float* postB,
                     const half_t* R, long long rS, int act)
{
    GemmArgs a;
    a.A = A; a.O = O; a.Cin = Cin; a.wS = wS;
    a.B = B; a.bS = bS;
    a.oF = oF; a.oS = oS; a.oT = oT;
    a.Y = Y; a.yS = yS;
    a.pre = pre; a.g = g; a.post = post; a.postB = postB;
    a.R = R; a.rS = rS; a.act = act;
    dim3 grid(GN / 128, (O + 127) / 128, GB);
    gemm_mma<<<grid, 256, SMEM_GEMM>>>(a);
}

extern "C" void kernel_launch(void* const* d_in, const int* in_sizes, int n_in,
                              void* d_out, int out_size)
{
#define FIN(i) ((const float*)d_in[i])
    const float *pts = FIN(0), *label = FIN(1), *We1 = FIN(2), *ge1 = FIN(3), *be1 = FIN(4),
                *We2 = FIN(5), *ge2 = FIN(6), *be2 = FIN(7), *W1 = FIN(8), *g1 = FIN(9),
                *b1 = FIN(10), *W2 = FIN(11), *g2 = FIN(12), *b2 = FIN(13), *Wf = FIN(14),
                *gf = FIN(15), *bf_ = FIN(16), *Wl = FIN(17), *gl = FIN(18), *bl = FIN(19),
                *Wc1 = FIN(20), *bc1 = FIN(21), *gc1 = FIN(22), *bb1 = FIN(23), *Wc2 = FIN(24),
                *bc2 = FIN(25), *gc2 = FIN(26), *bb2 = FIN(27), *Wc3 = FIN(28), *bc3 = FIN(29);
#undef FIN
    float* out = (float*)d_out;

    half_t *E1 = symp<half_t>(g_E1), *H = symp<half_t>(g_H), *M = symp<half_t>(g_M);
    half_t *T = symp<half_t>(g_T), *XC = symp<half_t>(g_XC), *XF = symp<half_t>(g_XF);
    half_t *C1 = symp<half_t>(g_C1), *C2 = symp<half_t>(g_C2);
    float *RMAX = symp<float>(g_RMAX), *RAVG = symp<float>(g_RAVG), *B1 = symp<float>(g_B1);
    int* IDX = symp<int>(g_IDX);
    half_t *hWe2 = symp<half_t>(g_We2), *hW1 = symp<half_t>(g_W1), *hW2 = symp<half_t>(g_W2);
    half_t *hWf = symp<half_t>(g_Wf), *hWc1 = symp<half_t>(g_Wc1);
    half_t *hWc2 = symp<half_t>(g_Wc2), *hWc3 = symp<half_t>(g_Wc3);

    // weight conversion
    convw_kernel<<<64, 256>>>(We2, hWe2, 16384);
    convw_kernel<<<192, 256>>>(W1, hW1, 49152);
    convw_kernel<<<192, 256>>>(W2, hW2, 49152);
    convw_kernel<<<1536, 256>>>(Wf, hWf, 393216);
    convw_kernel<<<6272, 256>>>(Wc1, hWc1, 1605632);
    convw_kernel<<<512, 256>>>(Wc2, hWc2, 131072);
    convw_kernel<<<50, 256>>>(Wc3, hWc3, 12800);

    // 1. KNN
    knn_kernel<<<dim3(GB, GN / 128), 128>>>(pts, IDX);

    // 2. embedding
    e1_kernel<<<dim3(GB, GN / 256), 256>>>(pts, We1, ge1, be1, E1);
    run_gemm(hWe2, 128, 128, 128, E1, 128LL * GN,
             nullptr, 0, nullptr, H, 128LL * GN,
             nullptr, ge2, be2, nullptr, nullptr, 0, 1);

    // 3. three edge blocks
    const half_t* h = H;
    long long hB = 128LL * GN;
    for (int i = 0; i < 3; ++i) {
        // t = relu(bn(W1 h)) -> T fp16 NC (for gather)
        run_gemm(hW1 + (long long)i * 16384, 128, 128, 128, h, hB,
                 nullptr, 0, T, nullptr, 0,
                 nullptr, g1 + i * 128, b1 + i * 128, nullptr, nullptr, 0, 1);
        gathermax_kernel<<<dim3(GB, GN / 8), 256>>>(T, IDX, M);
        // h = relu(bn(W2 m) + h) -> XC segment i (CN)
        run_gemm(hW2 + (long long)i * 16384, 128, 128, 128, M, 128LL * GN,
                 nullptr, 0, nullptr,
                 XC + (long long)i * 128 * GN, 384LL * GN,
                 nullptr, g2 + i * 128, b2 + i * 128, nullptr, h, hB, 1);
        h = XC + (long long)i * 128 * GN;
        hB = 384LL * GN;
    }

    // 4. xf = leaky(bn(Wf @ xcat))
    run_gemm(hWf, 1024, 384, 384, XC, 384LL * GN,
             nullptr, 0, nullptr, XF, 1024LL * GN,
             nullptr, gf, bf_, nullptr, nullptr, 0, 2);

    // 5. global reductions + per-batch bias for c1
    reduce_kernel<<<GB * 1024 / 8, 256>>>(XF, RMAX, RAVG);
    bias1_kernel<<<dim3(GB, 64), 256>>>(Wc1, bc1, gc1, bb1, Wl, gl, bl, label,
                                        RMAX, RAVG, B1);

    // 6. c1 = relu(gc1 * Wc1[:, :1024]@xf + per-batch bias)
    run_gemm(hWc1, 512, 1024, 3136, XF, 1024LL * GN,
             nullptr, 0, nullptr, C1, 512LL * GN,
             nullptr, gc1, nullptr, B1, nullptr, 0, 1);

    // 7. c2 = relu((Wc2@c1 + bc2)*gc2 + bb2)
    run_gemm(hWc2, 256, 512, 512, C1, 512LL * GN,
             nullptr, 0, nullptr, C2, 256LL * GN,
             bc2, gc2, bb2, nullptr, nullptr, 0, 1);

    // 8. out = Wc3@c2 + bc3  (fp32 CN)
    run_gemm(hWc3, 50, 256, 256, C2, 256LL * GN,
             out, 50LL * GN, nullptr, nullptr, 0,
             bc3, nullptr, nullptr, nullptr, nullptr, 0, 0);
}

// round 10
// speedup vs baseline: 1.4887x; 1.0064x over previous
#include <cuda_runtime.h>
#include <cuda_fp16.h>
#include <cstdint>

#define GN 2048
#define GB 16
typedef __half half_t;

// ---------------- scratch (static device globals; no allocation) ----------------
// Activations channel-major (CN): X[(b*C + c)*GN + n], single fp16 plane.
__device__ __align__(16) half_t g_E1[GB*128*GN];
__device__ __align__(16) half_t g_H [GB*128*GN];
__device__ __align__(16) half_t g_M [GB*128*GN];
__device__ __align__(16) half_t g_T [(size_t)GB*GN*128];           // NC for gather
__device__ __align__(16) half_t g_XC[(size_t)GB*384*GN];
__device__ __align__(16) half_t g_XF[(size_t)GB*1024*GN];
__device__ __align__(16) half_t g_C1[(size_t)GB*512*GN];
__device__ __align__(16) half_t g_C2[(size_t)GB*256*GN];
__device__ int   g_IDX [GB*GN*16];
__device__ float g_RMAX[GB*1024], g_RAVG[GB*1024], g_B1[GB*512];
// fp16 weights
__device__ __align__(16) half_t g_We2[16384];
__device__ __align__(16) half_t g_W1 [49152];
__device__ __align__(16) half_t g_W2 [49152];
__device__ __align__(16) half_t g_Wf [393216];
__device__ __align__(16) half_t g_Wc1[1605632];
__device__ __align__(16) half_t g_Wc2[131072];
__device__ __align__(16) half_t g_Wc3[12800];

// ---------------- weight fp32 -> fp16 ----------------
__global__ void convw_kernel(const float* __restrict__ w, half_t* __restrict__ o, int n)
{
    int i = blockIdx.x * 256 + threadIdx.x;
    if (i < n) o[i] = __float2half_rn(w[i]);
}

// ---------------- KNN: per-thread register top-16 ----------------
__global__ void knn_kernel(const float* __restrict__ pts, int* __restrict__ idxout)
{
    __shared__ float4 tile[256];
    int b = blockIdx.x;
    int n = blockIdx.y * 128 + threadIdx.x;
    const float* pb = pts + (long long)b * 6 * GN;
    float px = pb[n], py = pb[GN + n], pz = pb[2 * GN + n];
    float sp = px * px + py * py + pz * pz;

    float best[16];
    int   bidx[16];
#pragma unroll
    for (int i = 0; i < 16; ++i) { best[i] = 3.4e38f; bidx[i] = 0; }

    for (int t0 = 0; t0 < GN; t0 += 256) {
        __syncthreads();
        for (int i = threadIdx.x; i < 256; i += 128) {
            int m = t0 + i;
            float qx = pb[m], qy = pb[GN + m], qz = pb[2 * GN + m];
            tile[i] = make_float4(qx, qy, qz, qx * qx + qy * qy + qz * qz);
        }
        __syncthreads();
        for (int i = 0; i < 256; ++i) {
            float4 q = tile[i];
            float d = sp + q.w - 2.0f * (px * q.x + py * q.y + pz * q.z);
            if (d < best[15]) {
                int cand = t0 + i;
                int pos = 0;
#pragma unroll
                for (int k = 0; k < 16; ++k) pos += (best[k] <= d);
#pragma unroll
                for (int k = 15; k > 0; --k) {
                    if (k > pos) { best[k] = best[k - 1]; bidx[k] = bidx[k - 1]; }
                }
#pragma unroll
                for (int k = 0; k < 16; ++k)
                    if (k == pos) { best[k] = d; bidx[k] = cand; }
            }
        }
    }
    int* op = idxout + ((long long)b * GN + n) * 16;
#pragma unroll
    for (int i = 0; i < 16; ++i) op[i] = bidx[i];
}

// ---------------- e1: Cin=6 pointwise conv -> fp16 (CN) ----------------
__global__ void e1_kernel(const float* __restrict__ pts, const float* __restrict__ W,
                          const float* __restrict__ g, const float* __restrict__ bb,
                          half_t* __restrict__ out)
{
    __shared__ float Wsh[768], gs[128], bs[128];
    int b = blockIdx.x, tid = threadIdx.x;
    int n = blockIdx.y * 256 + tid;
    for (int i = tid; i < 768; i += 256) Wsh[i] = W[i];
    if (tid < 128) { gs[tid] = g[tid]; bs[tid] = bb[tid]; }
    __syncthreads();
    float x[6];
#pragma unroll
    for (int c = 0; c < 6; ++c) x[c] = pts[((long long)b * 6 + c) * GN + n];
    for (int o = 0; o < 128; ++o) {
        float s = 0.f;
#pragma unroll
        for (int c = 0; c < 6; ++c) s += Wsh[o * 6 + c] * x[c];
        s = fmaxf(s * gs[o] + bs[o], 0.f);
        out[((size_t)b * 128 + o) * GN + n] = __float2half_rn(s);
    }
}

// ---------------- fp16 tensor-core GEMM (mma.sync) ----------------
struct GemmArgs {
    const half_t* A; int O, Cin, wS;        // weights, row-major O x wS
    const half_t* B; long long bS;          // activations CN
    float* oF; long long oS;                // optional fp32 CN out
    half_t* oT;                             // optional fp16 NC out (T for gather)
    half_t* Y; long long yS;                // fp16 CN out
    const float *pre, *g, *post, *postB;
    const half_t* R; long long rS;          // residual CN fp16
    int act;
};

__device__ __forceinline__ uint32_t s2u(const void* p) {
    return (uint32_t)__cvta_generic_to_shared(p);
}
__device__ __forceinline__ void ldm4(uint32_t* r, uint32_t a) {
    asm volatile("ldmatrix.sync.aligned.m8n8.x4.shared.b16 {%0,%1,%2,%3},[%4];\n"
                 : "=r"(r[0]), "=r"(r[1]), "=r"(r[2]), "=r"(r[3]) : "r"(a));
}
__device__ __forceinline__ void ldm4t(uint32_t* r, uint32_t a) {
    asm volatile("ldmatrix.sync.aligned.m8n8.x4.trans.shared.b16 {%0,%1,%2,%3},[%4];\n"
                 : "=r"(r[0]), "=r"(r[1]), "=r"(r[2]), "=r"(r[3]) : "r"(a));
}
__device__ __forceinline__ void mma16816(float* d, const uint32_t* A, uint32_t b0, uint32_t b1) {
    asm volatile(
        "mma.sync.aligned.m16n8k16.row.col.f32.f16.f16.f32 "
        "{%0,%1,%2,%3},{%4,%5,%6,%7},{%8,%9},{%0,%1,%2,%3};\n"
        : "+f"(d[0]), "+f"(d[1]), "+f"(d[2]), "+f"(d[3])
        : "r"(A[0]), "r"(A[1]), "r"(A[2]), "r"(A[3]), "r"(b0), "r"(b1));
}

// smem (3 stages): A [3][128][40]half (row 80B) = 30720B ; B [3][32][136]half (row 272B) = 26112B
// epilogue reuses the same region as a 128x136-half staging tile (34816B)
#define SM_AS   10240
#define SM_BOFF 30720
#define SM_BS   8704
#define SMEM_GEMM 56832

__global__ void __launch_bounds__(256, 2) gemm_mma(GemmArgs A_)
{
    extern __shared__ char sm[];
    const int tid = threadIdx.x, lane = tid & 31, wid = tid >> 5;
    const int wm = wid & 1, wn = wid >> 1;
    const int b = blockIdx.z, n0 = blockIdx.x * 128, o0 = blockIdx.y * 128;
    const half_t* Bp = A_.B + (long long)b * A_.bS + n0;

    float acc[4][4][4];
#pragma unroll
    for (int i = 0; i < 4; ++i)
#pragma unroll
        for (int j = 0; j < 4; ++j)
#pragma unroll
            for (int k = 0; k < 4; ++k) acc[i][j][k] = 0.f;

    const int nch = A_.Cin >> 5;

    auto issue = [&](int buf, int c0) {
#pragma unroll
        for (int e = 0; e < 2; ++e) {               // A: 512 16B chunks
            int idx = tid + e * 256;
            int kc = idx & 3, row = idx >> 2;
            int o = o0 + row;
            bool ok = (o < A_.O);
            const half_t* src = ok ? A_.A + (long long)o * A_.wS + c0 + kc * 8 : A_.A;
            uint32_t dst = s2u(sm + (buf * SM_AS + row * 80 + kc * 16));
            int sz = ok ? 16 : 0;
            asm volatile("cp.async.ca.shared.global [%0],[%1],16,%2;\n"
                         :: "r"(dst), "l"(src), "r"(sz));
        }
#pragma unroll
        for (int e = 0; e < 2; ++e) {               // B: 512 16B chunks
            int idx = tid + e * 256;
            int kc = idx & 15, row = idx >> 4;
            const half_t* src = Bp + (long long)(c0 + row) * GN + kc * 8;
            uint32_t dst = s2u(sm + SM_BOFF + (buf * SM_BS + row * 272 + kc * 16));
            asm volatile("cp.async.ca.shared.global [%0],[%1],16,16;\n"
                         :: "r"(dst), "l"(src));
        }
        asm volatile("cp.async.commit_group;\n");
    };

    const int g8 = lane >> 3, r8 = lane & 7;
    const int rowIn16 = r8 + (g8 & 1) * 8;
    const int colOff  = (g8 >> 1) * 8;

    auto compute = [&](int buf) {
#pragma unroll
        for (int ks = 0; ks < 2; ++ks) {
            uint32_t ah[4][4];
#pragma unroll
            for (int mt = 0; mt < 4; ++mt) {
                int row = wm * 64 + mt * 16 + rowIn16;
                uint32_t aH = s2u(sm + buf * SM_AS + row * 80 + (ks * 16 + colOff) * 2);
                ldm4(ah[mt], aH);
            }
#pragma unroll
            for (int nt2 = 0; nt2 < 2; ++nt2) {
                int brow = ks * 16 + rowIn16;
                int bcol = wn * 32 + nt2 * 16 + colOff;
                uint32_t bH = s2u(sm + SM_BOFF + buf * SM_BS + brow * 272 + bcol * 2);
                uint32_t bh[4];
                ldm4t(bh, bH);
#pragma unroll
                for (int mt = 0; mt < 4; ++mt) {
                    mma16816(acc[mt][nt2 * 2],     ah[mt], bh[0], bh[1]);
                    mma16816(acc[mt][nt2 * 2 + 1], ah[mt], bh[2], bh[3]);
                }
            }
        }
    };

    // 3-stage pipeline: issue c+2 BEFORE waiting on c
    issue(0, 0);
    if (nch > 1) issue(1, 32);
    for (int c = 0; c < nch; ++c) {
        int buf = c % 3;
        if (c + 2 < nch) {
            issue((c + 2) % 3, (c + 2) * 32);
            asm volatile("cp.async.wait_group 2;\n");
        } else if (c + 1 < nch) {
            asm volatile("cp.async.wait_group 1;\n");
        } else {
            asm volatile("cp.async.wait_group 0;\n");
        }
        __syncthreads();
        compute(buf);
        __syncthreads();
    }

    // --- epilogue ---
    half_t* sT = (half_t*)sm;       // 128 x 136 staging tile (reuses mainloop smem)
    const int q = lane >> 2, tcol = (lane & 3) * 2;
#pragma unroll
    for (int mt = 0; mt < 4; ++mt) {
        int oBase = o0 + wm * 64 + mt * 16;
#pragma unroll
        for (int hh = 0; hh < 2; ++hh) {
            int o = oBase + q + hh * 8;
            if (o >= A_.O) continue;
            float pr = A_.pre  ? A_.pre[o]           : 0.f;
            float gg = A_.g    ? A_.g[o]             : 1.f;
            float po = A_.post ? A_.post[o]          : 0.f;
            if (A_.postB) po += A_.postB[b * A_.O + o];
            long long rowOff = (long long)o * GN;
#pragma unroll
            for (int nt = 0; nt < 4; ++nt) {
                int n = n0 + wn * 32 + nt * 8 + tcol;
                float v0 = (acc[mt][nt][hh * 2 + 0] + pr) * gg + po;
                float v1 = (acc[mt][nt][hh * 2 + 1] + pr) * gg + po;
                if (A_.R) {
                    const __half2 r2 = *(const __half2*)(A_.R + (long long)b * A_.rS + rowOff + n);
                    float2 rf = __half22float2(r2);
                    v0 += rf.x; v1 += rf.y;
                }
                if (A_.act == 1) { v0 = fmaxf(v0, 0.f); v1 = fmaxf(v1, 0.f); }
                else if (A_.act == 2) { v0 = v0 > 0.f ? v0 : 0.2f * v0; v1 = v1 > 0.f ? v1 : 0.2f * v1; }
                if (A_.Y) {
                    __half2 hp = __floats2half2_rn(v0, v1);
                    *(__half2*)(A_.Y + (long long)b * A_.yS + rowOff + n) = hp;
                }
                if (A_.oT) {       // stage fp16 NC into smem; coalesced flush below
                    int nl = n - n0, ol = o - o0;
                    sT[nl * 136 + ol] = __float2half_rn(v0);
                    sT[(nl + 1) * 136 + ol] = __float2half_rn(v1);
                }
                if (A_.oF) {
                    *(float2*)(A_.oF + (long long)b * A_.oS + rowOff + n) = make_float2(v0, v1);
                }
            }
        }
    }
    if (A_.oT) {
        __syncthreads();
        half_t* dst = A_.oT + ((long long)b * GN + n0) * 128;
#pragma unroll
        for (int e = 0; e < 8; ++e) {      // 128 rows x 16 uint4
            int i = tid + e * 256;
            int row = i >> 4, col = i & 15;
            uint4 v = *(uint4*)(sT + row * 136 + col * 8);
            *(uint4*)(dst + (long long)row * 128 + col * 8) = v;
        }
    }
}

// ---------------- gather + max (T fp16 NC in -> M fp16 CN out) ----------------
__global__ void gathermax_kernel(const half_t* __restrict__ T, const int* __restrict__ IDX,
                                 half_t* __restrict__ M)
{
    __shared__ float s[8][128];
    int b = blockIdx.x;
    int w = threadIdx.x >> 5, l = threadIdx.x & 31;
    int n0 = blockIdx.y * 8;
    int n = n0 + w;
    const half_t* tb = T + (size_t)b * GN * 128;
    const int* ib = IDX + ((size_t)b * GN + n) * 16;
    float4 best = make_float4(-3.4e38f, -3.4e38f, -3.4e38f, -3.4e38f);
#pragma unroll
    for (int k = 0; k < 16; ++k) {
        int j = ib[k];
        uint2 u = *((const uint2*)(tb + (size_t)j * 128) + l);   // 4 halves
        float2 a = __half22float2(*(__half2*)&u.x);
        float2 c = __half22float2(*(__half2*)&u.y);
        best.x = fmaxf(best.x, a.x); best.y = fmaxf(best.y, a.y);
        best.z = fmaxf(best.z, c.x); best.w = fmaxf(best.w, c.y);
    }
    s[w][l * 4 + 0] = best.x; s[w][l * 4 + 1] = best.y;
    s[w][l * 4 + 2] = best.z; s[w][l * 4 + 3] = best.w;
    __syncthreads();
    int c = threadIdx.x;
    if (c < 128) {
        __align__(16) half_t h8[8];
#pragma unroll
        for (int j = 0; j < 8; ++j) h8[j] = __float2half_rn(s[j][c]);
        *(uint4*)(M + ((size_t)b * 128 + c) * GN + n0) = *(uint4*)h8;
    }
}

// ---------------- row max+mean over N for XF (CN fp16) ----------------
__global__ void reduce_kernel(const half_t* __restrict__ XF,
                              float* __restrict__ RMAX, float* __restrict__ RAVG)
{
    int r = blockIdx.x * 8 + (threadIdx.x >> 5);
    int l = threadIdx.x & 31;
    const uint4* p = (const uint4*)(XF + (size_t)r * GN);   // 8 halves per uint4
    float mx = -3.4e38f, sm = 0.f;
#pragma unroll
    for (int t = 0; t < 8; ++t) {
        uint4 u = p[l + 32 * t];
        const uint32_t* uw = (const uint32_t*)&u;
#pragma unroll
        for (int i = 0; i < 4; ++i) {
            float2 f = __half22float2(*(const __half2*)&uw[i]);
            mx = fmaxf(mx, fmaxf(f.x, f.y));
            sm += f.x + f.y;
        }
    }
#pragma unroll
    for (int off = 16; off; off >>= 1) {
        mx = fmaxf(mx, __shfl_xor_sync(0xffffffffu, mx, off));
        sm += __shfl_xor_sync(0xffffffffu, sm, off);
    }
    if (!l) { RMAX[r] = mx; RAVG[r] = sm * (1.f / GN); }
}

// ---------------- per-batch bias for c1 ----------------
__global__ void bias1_kernel(const float* __restrict__ Wc1, const float* __restrict__ bc1,
                             const float* __restrict__ gc1, const float* __restrict__ bb1,
                             const float* __restrict__ Wl, const float* __restrict__ gl,
                             const float* __restrict__ bl, const float* __restrict__ label,
                             const float* __restrict__ RMAX, const float* __restrict__ RAVG,
                             float* __restrict__ B1)
{
    int b = blockIdx.x;
    int tid = threadIdx.x, warp = tid >> 5, lane = tid & 31;
    __shared__ float lab[64];
    if (tid < 64) {
        float s = 0.f;
#pragma unroll
        for (int i = 0; i < 16; ++i) s += Wl[tid * 16 + i] * label[b * 16 + i];
        s = s * gl[tid] + bl[tid];
        lab[tid] = s > 0.f ? s : 0.2f * s;
    }
    __syncthreads();
    int o = blockIdx.y * 8 + warp;
    const float* wr = Wc1 + (long long)o * 3136;
    const float* xm = RMAX + b * 1024;
    const float* xa = RAVG + b * 1024;
    float s = 0.f;
    for (int j = lane; j < 1024; j += 32)
        s += wr[1024 + j] * xm[j] + wr[2048 + j] * xa[j];
    for (int j = lane; j < 64; j += 32)
        s += wr[3072 + j] * lab[j];
#pragma unroll
    for (int off = 16; off; off >>= 1) s += __shfl_xor_sync(0xffffffffu, s, off);
    if (!lane) B1[b * 512 + o] = gc1[o] * (s + bc1[o]) + bb1[o];
}

// ---------------- host side ----------------
template <class T>
static T* symp(const void* s) { void* p = nullptr; cudaGetSymbolAddress(&p, s); return (T*)p; }

static void run_gemm(const half_t* A, int O, int Cin, int wS,
                     const half_t* B, long long bS,
                     float* oF, long long oS, half_t* oT,
                     half_t* Y, long long yS,
                     const float* pre, const float* g, const float* post, const float* postB,
                     const half_t* R, long long rS, int act)
{
    GemmArgs a;
    a.A = A; a.O = O; a.Cin = Cin; a.wS = wS;
    a.B = B; a.bS = bS;
    a.oF = oF; a.oS = oS; a.oT = oT;
    a.Y = Y; a.yS = yS;
    a.pre = pre; a.g = g; a.post = post; a.postB = postB;
    a.R = R; a.rS = rS; a.act = act;
    dim3 grid(GN / 128, (O + 127) / 128, GB);
    gemm_mma<<<grid, 256, SMEM_GEMM>>>(a);
}

extern "C" void kernel_launch(void* const* d_in, const int* in_sizes, int n_in,
                              void* d_out, int out_size)
{
#define FIN(i) ((const float*)d_in[i])
    const float *pts = FIN(0), *label = FIN(1), *We1 = FIN(2), *ge1 = FIN(3), *be1 = FIN(4),
                *We2 = FIN(5), *ge2 = FIN(6), *be2 = FIN(7), *W1 = FIN(8), *g1 = FIN(9),
                *b1 = FIN(10), *W2 = FIN(11), *g2 = FIN(12), *b2 = FIN(13), *Wf = FIN(14),
                *gf = FIN(15), *bf_ = FIN(16), *Wl = FIN(17), *gl = FIN(18), *bl = FIN(19),
                *Wc1 = FIN(20), *bc1 = FIN(21), *gc1 = FIN(22), *bb1 = FIN(23), *Wc2 = FIN(24),
                *bc2 = FIN(25), *gc2 = FIN(26), *bb2 = FIN(27), *Wc3 = FIN(28), *bc3 = FIN(29);
#undef FIN
    float* out = (float*)d_out;

    cudaFuncSetAttribute(gemm_mma, cudaFuncAttributeMaxDynamicSharedMemorySize, SMEM_GEMM);

    half_t *E1 = symp<half_t>(g_E1), *H = symp<half_t>(g_H), *M = symp<half_t>(g_M);
    half_t *T = symp<half_t>(g_T), *XC = symp<half_t>(g_XC), *XF = symp<half_t>(g_XF);
    half_t *C1 = symp<half_t>(g_C1), *C2 = symp<half_t>(g_C2);
    float *RMAX = symp<float>(g_RMAX), *RAVG = symp<float>(g_RAVG), *B1 = symp<float>(g_B1);
    int* IDX = symp<int>(g_IDX);
    half_t *hWe2 = symp<half_t>(g_We2), *hW1 = symp<half_t>(g_W1), *hW2 = symp<half_t>(g_W2);
    half_t *hWf = symp<half_t>(g_Wf), *hWc1 = symp<half_t>(g_Wc1);
    half_t *hWc2 = symp<half_t>(g_Wc2), *hWc3 = symp<half_t>(g_Wc3);

    // weight conversion
    convw_kernel<<<64, 256>>>(We2, hWe2, 16384);
    convw_kernel<<<192, 256>>>(W1, hW1, 49152);
    convw_kernel<<<192, 256>>>(W2, hW2, 49152);
    convw_kernel<<<1536, 256>>>(Wf, hWf, 393216);
    convw_kernel<<<6272, 256>>>(Wc1, hWc1, 1605632);
    convw_kernel<<<512, 256>>>(Wc2, hWc2, 131072);
    convw_kernel<<<50, 256>>>(Wc3, hWc3, 12800);

    // 1. KNN
    knn_kernel<<<dim3(GB, GN / 128), 128>>>(pts, IDX);

    // 2. embedding
    e1_kernel<<<dim3(GB, GN / 256), 256>>>(pts, We1, ge1, be1, E1);
    run_gemm(hWe2, 128, 128, 128, E1, 128LL * GN,
             nullptr, 0, nullptr, H, 128LL * GN,
             nullptr, ge2, be2, nullptr, nullptr, 0, 1);

    // 3. three edge blocks
    const half_t* h = H;
    long long hB = 128LL * GN;
    for (int i = 0; i < 3; ++i) {
        // t = relu(bn(W1 h)) -> T fp16 NC (for gather)
        run_gemm(hW1 + (long long)i * 16384, 128, 128, 128, h, hB,
                 nullptr, 0, T, nullptr, 0,
                 nullptr, g1 + i * 128, b1 + i * 128, nullptr, nullptr, 0, 1);
        gathermax_kernel<<<dim3(GB, GN / 8), 256>>>(T, IDX, M);
        // h = relu(bn(W2 m) + h) -> XC segment i (CN)
        run_gemm(hW2 + (long long)i * 16384, 128, 128, 128, M, 128LL * GN,
                 nullptr, 0, nullptr,
                 XC + (long long)i * 128 * GN, 384LL * GN,
                 nullptr, g2 + i * 128, b2 + i * 128, nullptr, h, hB, 1);
        h = XC + (long long)i * 128 * GN;
        hB = 384LL * GN;
    }

    // 4. xf = leaky(bn(Wf @ xcat))
    run_gemm(hWf, 1024, 384, 384, XC, 384LL * GN,
             nullptr, 0, nullptr, XF, 1024LL * GN,
             nullptr, gf, bf_, nullptr, nullptr, 0, 2);

    // 5. global reductions + per-batch bias for c1
    reduce_kernel<<<GB * 1024 / 8, 256>>>(XF, RMAX, RAVG);
    bias1_kernel<<<dim3(GB, 64), 256>>>(Wc1, bc1, gc1, bb1, Wl, gl, bl, label,
                                        RMAX, RAVG, B1);

    // 6. c1 = relu(gc1 * Wc1[:, :1024]@xf + per-batch bias)
    run_gemm(hWc1, 512, 1024, 3136, XF, 1024LL * GN,
             nullptr, 0, nullptr, C1, 512LL * GN,
             nullptr, gc1, nullptr, B1, nullptr, 0, 1);

    // 7. c2 = relu((Wc2@c1 + bc2)*gc2 + bb2)
    run_gemm(hWc2, 256, 512, 512, C1, 512LL * GN,
             nullptr, 0, nullptr, C2, 256LL * GN,
             bc2, gc2, bb2, nullptr, nullptr, 0, 1);

    // 8. out = Wc3@c2 + bc3  (fp32 CN)
    run_gemm(hWc3, 50, 256, 256, C2, 256LL * GN,
             out, 50LL * GN, nullptr, nullptr, 0,
             bc3, nullptr, nullptr, nullptr, nullptr, 0, 0);
}